// round 10
// baseline (speedup 1.0000x reference)
#include <cuda_runtime.h>

// DynamicUpsamplingFilter:
//   x:       (1, 3, 25, 128, 128) float32          -> d_in[0]
//   filters: (1, 25, 16, 25, 128, 128) float32     -> d_in[1]
//   out:     (1, 48, 25, 128, 128) float32
// out[c*16+u, t, h, w] = sum_{a,b} x[c, t, h+a-2, w+b-2] * filters[a*5+b, u, t, h, w]
//
// R10: R9 with __ldcs reverted to __ldg on the filter stream (evict-first
// marking cost ~2% achieved BW in both R2 and R9). Keeps:
//  - UG=2, 7 CTAs/SM (28 warps), full a-unroll (software-pipelined loads)
//  - float4 LDG / conflict-free float4 LDS windows
//  - __stcs streaming stores
//  - grid = (2, 3200): u-half pairs adjacent in launch order -> x L2 reuse

#define T_DIM 25
#define H_DIM 128
#define W_DIM 128
#define HW    (H_DIM * W_DIM)       // 16384
#define THW   (T_DIM * HW)          // 409600
#define C_IN  3
#define KH    5
#define KW    5
#define UPSQ  16
#define UG    2                     // u per thread

__global__ __launch_bounds__(128, 7)
void duf_kernel(const float* __restrict__ x,
                const float* __restrict__ f,
                float* __restrict__ out)
{
    const int tid = threadIdx.x;
    const int w4  = tid & 31;            // float4 index over w
    const int ug  = tid >> 5;            // 0..3
    const int w0  = w4 << 2;
    const int h = blockIdx.y & (H_DIM - 1);
    const int t = blockIdx.y >> 7;
    const int u0 = blockIdx.x * 8 + ug * UG;   // first u of this thread

    // x patch tile: 3 channels x 5 rows x (128 + 4) cols, zero halo in w.
    __shared__ __align__(16) float sx[C_IN][KH][W_DIM + 4];

    if (tid < 2) {
        #pragma unroll
        for (int c = 0; c < C_IN; c++)
            #pragma unroll
            for (int a = 0; a < KH; a++) {
                sx[c][a][tid] = 0.0f;
                sx[c][a][W_DIM + 2 + tid] = 0.0f;
            }
    }

    // stage x rows h-2..h+2 for all 3 channels (tid = w index here)
    #pragma unroll
    for (int c = 0; c < C_IN; c++) {
        #pragma unroll
        for (int a = 0; a < KH; a++) {
            const int hh = h + a - 2;
            float v = 0.0f;
            if (hh >= 0 && hh < H_DIM)
                v = __ldg(&x[c * THW + t * HW + hh * W_DIM + tid]);
            sx[c][a][tid + 2] = v;
        }
    }
    __syncthreads();

    const int rowbase = t * HW + h * W_DIM;
    // filter pointer for (k=0, u=u0, this row, w0)
    const float4* fp = (const float4*)(f + (size_t)u0 * THW + rowbase + w0);

    float4 acc[C_IN][UG];
    #pragma unroll
    for (int c = 0; c < C_IN; c++)
        #pragma unroll
        for (int j = 0; j < UG; j++)
            acc[c][j] = make_float4(0.f, 0.f, 0.f, 0.f);

    // FULL unroll: ptxas pipelines next iteration's loads over this
    // iteration's FMAs.
    #pragma unroll
    for (int a = 0; a < KH; a++) {
        // conflict-free window: 8 floats per channel as two aligned LDS.128
        float win[C_IN][8];
        #pragma unroll
        for (int c = 0; c < C_IN; c++) {
            const float4 lo = *(const float4*)&sx[c][a][w0];
            const float4 hi = *(const float4*)&sx[c][a][w0 + 4];
            win[c][0] = lo.x; win[c][1] = lo.y; win[c][2] = lo.z; win[c][3] = lo.w;
            win[c][4] = hi.x; win[c][5] = hi.y; win[c][6] = hi.z; win[c][7] = hi.w;
        }

        const float4* fa = fp + (size_t)(a * KW) * (UPSQ * THW / 4);

        #pragma unroll
        for (int b = 0; b < KW; b++) {
            const float4* fk = fa + (size_t)b * (UPSQ * THW / 4);
            float4 fv[UG];
            #pragma unroll
            for (int j = 0; j < UG; j++)
                fv[j] = __ldg(fk + (size_t)j * (THW / 4));

            #pragma unroll
            for (int c = 0; c < C_IN; c++) {
                const float p0 = win[c][b];
                const float p1 = win[c][b + 1];
                const float p2 = win[c][b + 2];
                const float p3 = win[c][b + 3];
                #pragma unroll
                for (int j = 0; j < UG; j++) {
                    acc[c][j].x = fmaf(p0, fv[j].x, acc[c][j].x);
                    acc[c][j].y = fmaf(p1, fv[j].y, acc[c][j].y);
                    acc[c][j].z = fmaf(p2, fv[j].z, acc[c][j].z);
                    acc[c][j].w = fmaf(p3, fv[j].w, acc[c][j].w);
                }
            }
        }
    }

    // out[(c*16 + u0 + j)*THW + rowbase + w0], 512B/warp streaming stores
    float4* op = (float4*)(out + (size_t)u0 * THW + rowbase + w0);
    #pragma unroll
    for (int c = 0; c < C_IN; c++)
        #pragma unroll
        for (int j = 0; j < UG; j++)
            __stcs(&op[((size_t)c * UPSQ + j) * (THW / 4)], acc[c][j]);
}

extern "C" void kernel_launch(void* const* d_in, const int* in_sizes, int n_in,
                              void* d_out, int out_size)
{
    const float* x = (const float*)d_in[0];
    const float* f = (const float*)d_in[1];
    float* out = (float*)d_out;

    dim3 grid(2, T_DIM * H_DIM);  // (u-half, t*h row): pairs adjacent in launch order
    dim3 block(128);
    duf_kernel<<<grid, block>>>(x, f, out);
}

// round 11
// speedup vs baseline: 1.0158x; 1.0158x over previous
#include <cuda_runtime.h>

// DynamicUpsamplingFilter:
//   x:       (1, 3, 25, 128, 128) float32          -> d_in[0]
//   filters: (1, 25, 16, 25, 128, 128) float32     -> d_in[1]
//   out:     (1, 48, 25, 128, 128) float32
// out[c*16+u, t, h, w] = sum_{a,b} x[c, t, h+a-2, w+b-2] * filters[a*5+b, u, t, h, w]
//
// R11: R10 with __stwt (write-through) stores instead of __stcs.
// Write stream no longer allocates L2 lines -> filter/x lines stop being
// evicted by out writes (recovers R9's traffic saving without R9's
// __ldcs read-BW penalty). Reads stay __ldg (proven best BW).
//  - UG=2, 7 CTAs/SM (28 warps), full a-unroll (software-pipelined loads)
//  - float4 LDG / conflict-free float4 LDS windows
//  - grid = (2, 3200): u-half pairs adjacent in launch order -> x L2 reuse

#define T_DIM 25
#define H_DIM 128
#define W_DIM 128
#define HW    (H_DIM * W_DIM)       // 16384
#define THW   (T_DIM * HW)          // 409600
#define C_IN  3
#define KH    5
#define KW    5
#define UPSQ  16
#define UG    2                     // u per thread

__global__ __launch_bounds__(128, 7)
void duf_kernel(const float* __restrict__ x,
                const float* __restrict__ f,
                float* __restrict__ out)
{
    const int tid = threadIdx.x;
    const int w4  = tid & 31;            // float4 index over w
    const int ug  = tid >> 5;            // 0..3
    const int w0  = w4 << 2;
    const int h = blockIdx.y & (H_DIM - 1);
    const int t = blockIdx.y >> 7;
    const int u0 = blockIdx.x * 8 + ug * UG;   // first u of this thread

    // x patch tile: 3 channels x 5 rows x (128 + 4) cols, zero halo in w.
    __shared__ __align__(16) float sx[C_IN][KH][W_DIM + 4];

    if (tid < 2) {
        #pragma unroll
        for (int c = 0; c < C_IN; c++)
            #pragma unroll
            for (int a = 0; a < KH; a++) {
                sx[c][a][tid] = 0.0f;
                sx[c][a][W_DIM + 2 + tid] = 0.0f;
            }
    }

    // stage x rows h-2..h+2 for all 3 channels (tid = w index here)
    #pragma unroll
    for (int c = 0; c < C_IN; c++) {
        #pragma unroll
        for (int a = 0; a < KH; a++) {
            const int hh = h + a - 2;
            float v = 0.0f;
            if (hh >= 0 && hh < H_DIM)
                v = __ldg(&x[c * THW + t * HW + hh * W_DIM + tid]);
            sx[c][a][tid + 2] = v;
        }
    }
    __syncthreads();

    const int rowbase = t * HW + h * W_DIM;
    // filter pointer for (k=0, u=u0, this row, w0)
    const float4* fp = (const float4*)(f + (size_t)u0 * THW + rowbase + w0);

    float4 acc[C_IN][UG];
    #pragma unroll
    for (int c = 0; c < C_IN; c++)
        #pragma unroll
        for (int j = 0; j < UG; j++)
            acc[c][j] = make_float4(0.f, 0.f, 0.f, 0.f);

    // FULL unroll: ptxas pipelines next iteration's loads over this
    // iteration's FMAs.
    #pragma unroll
    for (int a = 0; a < KH; a++) {
        // conflict-free window: 8 floats per channel as two aligned LDS.128
        float win[C_IN][8];
        #pragma unroll
        for (int c = 0; c < C_IN; c++) {
            const float4 lo = *(const float4*)&sx[c][a][w0];
            const float4 hi = *(const float4*)&sx[c][a][w0 + 4];
            win[c][0] = lo.x; win[c][1] = lo.y; win[c][2] = lo.z; win[c][3] = lo.w;
            win[c][4] = hi.x; win[c][5] = hi.y; win[c][6] = hi.z; win[c][7] = hi.w;
        }

        const float4* fa = fp + (size_t)(a * KW) * (UPSQ * THW / 4);

        #pragma unroll
        for (int b = 0; b < KW; b++) {
            const float4* fk = fa + (size_t)b * (UPSQ * THW / 4);
            float4 fv[UG];
            #pragma unroll
            for (int j = 0; j < UG; j++)
                fv[j] = __ldg(fk + (size_t)j * (THW / 4));

            #pragma unroll
            for (int c = 0; c < C_IN; c++) {
                const float p0 = win[c][b];
                const float p1 = win[c][b + 1];
                const float p2 = win[c][b + 2];
                const float p3 = win[c][b + 3];
                #pragma unroll
                for (int j = 0; j < UG; j++) {
                    acc[c][j].x = fmaf(p0, fv[j].x, acc[c][j].x);
                    acc[c][j].y = fmaf(p1, fv[j].y, acc[c][j].y);
                    acc[c][j].z = fmaf(p2, fv[j].z, acc[c][j].z);
                    acc[c][j].w = fmaf(p3, fv[j].w, acc[c][j].w);
                }
            }
        }
    }

    // out[(c*16 + u0 + j)*THW + rowbase + w0], 512B/warp write-through stores
    float4* op = (float4*)(out + (size_t)u0 * THW + rowbase + w0);
    #pragma unroll
    for (int c = 0; c < C_IN; c++)
        #pragma unroll
        for (int j = 0; j < UG; j++)
            __stwt(&op[((size_t)c * UPSQ + j) * (THW / 4)], acc[c][j]);
}

extern "C" void kernel_launch(void* const* d_in, const int* in_sizes, int n_in,
                              void* d_out, int out_size)
{
    const float* x = (const float*)d_in[0];
    const float* f = (const float*)d_in[1];
    float* out = (float*)d_out;

    dim3 grid(2, T_DIM * H_DIM);  // (u-half, t*h row): pairs adjacent in launch order
    dim3 block(128);
    duf_kernel<<<grid, block>>>(x, f, out);
}